// round 1
// baseline (speedup 1.0000x reference)
#include <cuda_runtime.h>
#include <math.h>

#define N_NODES 50000
#define N_EDGES 640000
#define N_GRAPHS 64
#define D 128

// ---------------- device scratch (no allocation allowed) ----------------
__device__ float g_xp[N_NODES * D];   // xp = h @ w_lin
__device__ float g_h [N_NODES * D];   // agg / h (reused across layers)
__device__ float g_si[N_NODES * 2];   // per-node dst-attention dots
__device__ float g_sj[N_NODES * 2];   // per-node src-attention dots
__device__ float g_ae[36];            // per-layer 6x2 edge-att projection (3*6*2)
__device__ float g_pool[N_GRAPHS * D];
__device__ float g_cnt[N_GRAPHS];
__device__ int   g_flags[2];          // [0]: edge_index is int64, [1]: batch is int64

// ---------------- dtype detection (int32 vs int64 delivery) -------------
// If data is int64 (values < 2^31), every odd 32-bit word is 0.
// If data is int32, odd words are random node/graph ids (nonzero w.h.p.).
// batch is sorted ascending, so sample near the TAIL (values ~63).
__global__ void detect_kernel(const int* __restrict__ ei32,
                              const int* __restrict__ b32) {
    __shared__ int s_e, s_b;
    int t = threadIdx.x;
    if (t == 0) { s_e = 0; s_b = 0; }
    __syncthreads();
    // edge: odd words spread over first row (safe for both widths)
    int ei_idx = 2 * (t * 257) + 1;                    // < 33k words, in-bounds either way
    if (ei32[ei_idx] != 0) atomicAdd(&s_e, 1);
    int b_idx = (N_NODES - 1) - 2 * t;                 // odd indices near tail
    if (b32[b_idx] != 0) atomicAdd(&s_b, 1);
    __syncthreads();
    if (t == 0) { g_flags[0] = (s_e == 0); g_flags[1] = (s_b == 0); }
}

// ------------- per-layer edge attention projection: ae[l][f][h] ----------
// ae = sum_c w_edge[f, h*64+c] * att[h*192 + 128 + c]     (6x2 per layer)
__global__ void attproj_kernel(const float* __restrict__ we0, const float* __restrict__ at0,
                               const float* __restrict__ we1, const float* __restrict__ at1,
                               const float* __restrict__ we2, const float* __restrict__ at2) {
    int t = threadIdx.x;
    if (t >= 36) return;
    int l = t / 12, r = t % 12, f = r / 2, h = r % 2;
    const float* we = (l == 0) ? we0 : (l == 1) ? we1 : we2;
    const float* at = (l == 0) ? at0 : (l == 1) ? at1 : at2;
    float s = 0.f;
    #pragma unroll
    for (int c = 0; c < 64; c++)
        s += we[f * 128 + h * 64 + c] * at[h * 192 + 128 + c];
    g_ae[t] = s;
}

// ---------------- layer-0 lin: x(N,7) @ w(7,128) -> g_xp -----------------
__global__ void lin0_kernel(const float* __restrict__ x, const float* __restrict__ w) {
    int idx = blockIdx.x * blockDim.x + threadIdx.x;
    if (idx >= N_NODES * D) return;
    int n = idx >> 7, c = idx & 127;
    const float* xr = x + n * 7;
    float s = 0.f;
    #pragma unroll
    for (int f = 0; f < 7; f++) s += xr[f] * w[f * 128 + c];
    g_xp[idx] = s;
}

// ------------- lin: hin(N,128) @ w(128,128) -> g_xp, tiled ---------------
// 64-row tile, 256 threads, each thread 4 rows x 8 cols (cols = tcol + 16*j
// so shared loads are stride-1 / conflict-free and stores coalesce).
__global__ void lin128_kernel(const float* __restrict__ hin, const float* __restrict__ w) {
    __shared__ float Xs[64][33];
    __shared__ float Ws[32][128];
    int t = threadIdx.x;
    int tcol = t & 15, trow = t >> 4;
    int row0 = blockIdx.x * 64;
    float acc[4][8];
    #pragma unroll
    for (int i = 0; i < 4; i++)
        #pragma unroll
        for (int j = 0; j < 8; j++) acc[i][j] = 0.f;

    for (int kc = 0; kc < 4; kc++) {
        int k0 = kc * 32;
        for (int i = t; i < 64 * 32; i += 256) {
            int r = i >> 5, k = i & 31, row = row0 + r;
            Xs[r][k] = (row < N_NODES) ? hin[row * 128 + k0 + k] : 0.f;
        }
        for (int i = t; i < 32 * 128; i += 256) {
            int kk = i >> 7, c = i & 127;
            Ws[kk][c] = w[(k0 + kk) * 128 + c];
        }
        __syncthreads();
        #pragma unroll
        for (int kk = 0; kk < 32; kk++) {
            float xv[4];
            #pragma unroll
            for (int i = 0; i < 4; i++) xv[i] = Xs[trow * 4 + i][kk];
            #pragma unroll
            for (int j = 0; j < 8; j++) {
                float wv = Ws[kk][tcol + 16 * j];
                #pragma unroll
                for (int i = 0; i < 4; i++) acc[i][j] += xv[i] * wv;
            }
        }
        __syncthreads();
    }
    #pragma unroll
    for (int i = 0; i < 4; i++) {
        int row = row0 + trow * 4 + i;
        if (row < N_NODES) {
            #pragma unroll
            for (int j = 0; j < 8; j++)
                g_xp[row * 128 + tcol + 16 * j] = acc[i][j];
        }
    }
}

// ------------- per-node attention dots: s_i, s_j from g_xp ---------------
__global__ void s_kernel(const float* __restrict__ att) {
    int gw   = (blockIdx.x * blockDim.x + threadIdx.x) >> 5;
    int lane = threadIdx.x & 31;
    if (gw >= N_NODES) return;
    const float* xr = g_xp + gw * 128;
    float v0 = xr[lane], v1 = xr[lane + 32], v2 = xr[lane + 64], v3 = xr[lane + 96];
    float si0 = v0 * att[lane]           + v1 * att[lane + 32];
    float sj0 = v0 * att[64 + lane]      + v1 * att[96 + lane];
    float si1 = v2 * att[192 + lane]     + v3 * att[192 + lane + 32];
    float sj1 = v2 * att[192 + 64 + lane]+ v3 * att[192 + 96 + lane];
    #pragma unroll
    for (int o = 16; o; o >>= 1) {
        si0 += __shfl_down_sync(0xffffffffu, si0, o);
        sj0 += __shfl_down_sync(0xffffffffu, sj0, o);
        si1 += __shfl_down_sync(0xffffffffu, si1, o);
        sj1 += __shfl_down_sync(0xffffffffu, sj1, o);
    }
    if (lane == 0) {
        g_si[gw * 2] = si0; g_si[gw * 2 + 1] = si1;
        g_sj[gw * 2] = sj0; g_sj[gw * 2 + 1] = sj1;
    }
}

// ------------- edge scatter: one warp per edge, vec4 red.global ----------
__global__ void edge_kernel(const void* __restrict__ ei,
                            const float* __restrict__ ea, int layer) {
    int warp = (blockIdx.x * blockDim.x + threadIdx.x) >> 5;
    int lane = threadIdx.x & 31;
    if (warp >= N_EDGES) return;
    int is64 = g_flags[0];
    long long src, dst;
    if (is64) {
        const long long* p = (const long long*)ei;
        src = p[warp]; dst = p[N_EDGES + warp];
    } else {
        const int* p = (const int*)ei;
        src = p[warp]; dst = p[N_EDGES + warp];
    }
    float w0, w1;
    if (lane == 0) {
        const float* ap = g_ae + layer * 12;
        const float* e6 = ea + (long long)warp * 6;
        float se0 = 0.f, se1 = 0.f;
        #pragma unroll
        for (int f = 0; f < 6; f++) {
            se0 += e6[f] * ap[f * 2];
            se1 += e6[f] * ap[f * 2 + 1];
        }
        float a0 = g_si[dst * 2]     + g_sj[src * 2]     + se0;
        float a1 = g_si[dst * 2 + 1] + g_sj[src * 2 + 1] + se1;
        a0 = a0 > 0.f ? a0 : 0.2f * a0;            // leaky_relu
        a1 = a1 > 0.f ? a1 : 0.2f * a1;
        float m  = fmaxf(a0, a1);
        float e0 = __expf(a0 - m), e1 = __expf(a1 - m);
        float inv = 1.f / (e0 + e1);
        w0 = e0 * inv; w1 = e1 * inv;              // softmax over the 2 heads
    }
    w0 = __shfl_sync(0xffffffffu, w0, 0);
    w1 = __shfl_sync(0xffffffffu, w1, 0);
    const float4* xv = (const float4*)(g_xp + src * 128);
    float4 v = xv[lane];
    float a = (lane < 16) ? w0 : w1;               // head0 = cols 0..63
    float* dp = g_h + dst * 128 + lane * 4;
    asm volatile("red.global.add.v4.f32 [%0], {%1,%2,%3,%4};"
                 :: "l"(dp), "f"(v.x * a), "f"(v.y * a), "f"(v.z * a), "f"(v.w * a)
                 : "memory");
}

// ------------- bias + relu in place on g_h -------------------------------
__global__ void biasrelu_kernel(const float* __restrict__ b) {
    int idx = blockIdx.x * blockDim.x + threadIdx.x;
    if (idx >= N_NODES * D) return;
    float v = g_h[idx] + b[idx & 127];
    g_h[idx] = v > 0.f ? v : 0.f;
}

// ------------- mean pool: batch is sorted, run-length local accum --------
__global__ void pool_kernel(const void* __restrict__ batch) {
    const int NPB = 128;
    int t  = threadIdx.x;              // column
    int n0 = blockIdx.x * NPB;
    int is64 = g_flags[1];
    float acc = 0.f; int cur = -1; int run = 0;
    for (int k = 0; k < NPB; k++) {
        int n = n0 + k;
        if (n >= N_NODES) break;
        int g = is64 ? (int)((const long long*)batch)[n] : ((const int*)batch)[n];
        if (g != cur) {
            if (cur >= 0) {
                atomicAdd(&g_pool[cur * D + t], acc);
                if (t == 0) atomicAdd(&g_cnt[cur], (float)run);
            }
            acc = 0.f; run = 0; cur = g;
        }
        acc += g_h[n * D + t]; run++;
    }
    if (cur >= 0) {
        atomicAdd(&g_pool[cur * D + t], acc);
        if (t == 0) atomicAdd(&g_cnt[cur], (float)run);
    }
}

// ------------- final: mean, linear(128->2), log_softmax ------------------
__global__ void final_kernel(const float* __restrict__ wout,
                             const float* __restrict__ bout,
                             float* __restrict__ out) {
    int g = threadIdx.x;
    if (g >= N_GRAPHS) return;
    float inv = 1.f / fmaxf(g_cnt[g], 1.f);
    float z0 = bout[0], z1 = bout[1];
    for (int c = 0; c < D; c++) {
        float p = g_pool[g * D + c] * inv;
        z0 += p * wout[c * 2];
        z1 += p * wout[c * 2 + 1];
    }
    float m = fmaxf(z0, z1);
    float l = m + logf(expf(z0 - m) + expf(z1 - m));
    out[g * 2]     = z0 - l;
    out[g * 2 + 1] = z1 - l;
}

// ------------------------------ launch -----------------------------------
extern "C" void kernel_launch(void* const* d_in, const int* in_sizes, int n_in,
                              void* d_out, int out_size) {
    const float* x     = (const float*)d_in[0];
    const void*  ei    = d_in[1];
    const float* ea    = (const float*)d_in[2];
    const void*  batch = d_in[3];
    const float* wl[3]  = { (const float*)d_in[4],  (const float*)d_in[8],  (const float*)d_in[12] };
    const float* we[3]  = { (const float*)d_in[5],  (const float*)d_in[9],  (const float*)d_in[13] };
    const float* att[3] = { (const float*)d_in[6],  (const float*)d_in[10], (const float*)d_in[14] };
    const float* bb[3]  = { (const float*)d_in[7],  (const float*)d_in[11], (const float*)d_in[15] };
    const float* wout = (const float*)d_in[16];
    const float* bout = (const float*)d_in[17];

    void *p_h = nullptr, *p_pool = nullptr, *p_cnt = nullptr;
    cudaGetSymbolAddress(&p_h,    g_h);
    cudaGetSymbolAddress(&p_pool, g_pool);
    cudaGetSymbolAddress(&p_cnt,  g_cnt);

    detect_kernel<<<1, 64>>>((const int*)ei, (const int*)batch);
    attproj_kernel<<<1, 64>>>(we[0], att[0], we[1], att[1], we[2], att[2]);

    const int ND = N_NODES * D;
    for (int l = 0; l < 3; l++) {
        if (l == 0) lin0_kernel<<<(ND + 255) / 256, 256>>>(x, wl[0]);
        else        lin128_kernel<<<(N_NODES + 63) / 64, 256>>>((const float*)p_h, wl[l]);
        s_kernel<<<(N_NODES * 32 + 255) / 256, 256>>>(att[l]);
        cudaMemsetAsync(p_h, 0, (size_t)ND * sizeof(float));
        edge_kernel<<<N_EDGES / 8, 256>>>(ei, ea, l);
        biasrelu_kernel<<<(ND + 255) / 256, 256>>>(bb[l]);
    }

    cudaMemsetAsync(p_pool, 0, (size_t)N_GRAPHS * D * sizeof(float));
    cudaMemsetAsync(p_cnt,  0, (size_t)N_GRAPHS * sizeof(float));
    pool_kernel<<<(N_NODES + 127) / 128, 128>>>(batch);
    final_kernel<<<1, 64>>>(wout, bout, (float*)d_out);
}

// round 2
// speedup vs baseline: 1.4210x; 1.4210x over previous
#include <cuda_runtime.h>
#include <math.h>

#define N_NODES 50000
#define N_EDGES 640000
#define N_GRAPHS 64
#define D 128

// ---------------- device scratch (no allocation allowed) ----------------
__device__ float  g_xp[N_NODES * D];     // xp = h @ w_lin
__device__ float  g_h [N_NODES * D];     // layer output (bias+relu applied)
__device__ float2 g_si[N_NODES];         // per-node dst-attention dots (2 heads)
__device__ float2 g_sj[N_NODES];         // per-node src-attention dots
__device__ float  g_ae[36];              // 3 layers x 6 feats x 2 heads
__device__ float  g_se[N_EDGES * 6];     // per-edge edge-att scores, 3 layers x 2 heads
__device__ float2 g_ws[N_EDGES];         // softmax weights, permuted into dst order
__device__ int    g_srcs[N_EDGES];       // src ids sorted by dst
__device__ int    g_perm[N_EDGES];       // edge e -> position in dst-sorted order
__device__ int    g_deg[N_NODES];
__device__ int    g_off[N_NODES + 1];
__device__ int    g_cur[N_NODES];
__device__ float  g_pool[N_GRAPHS * D];
__device__ float  g_cnt[N_GRAPHS];
__device__ int    g_flags[2];            // [0]: edge_index is int64, [1]: batch is int64

// ---------------- dtype detection (int32 vs int64 delivery) -------------
__global__ void detect_kernel(const int* __restrict__ ei32,
                              const int* __restrict__ b32) {
    __shared__ int s_e, s_b;
    int t = threadIdx.x;
    if (t == 0) { s_e = 0; s_b = 0; }
    __syncthreads();
    int ei_idx = 2 * (t * 257) + 1;
    if (ei32[ei_idx] != 0) atomicAdd(&s_e, 1);
    int b_idx = (N_NODES - 1) - 2 * t;
    if (b32[b_idx] != 0) atomicAdd(&s_b, 1);
    __syncthreads();
    if (t == 0) { g_flags[0] = (s_e == 0); g_flags[1] = (s_b == 0); }
}

__device__ __forceinline__ void load_edge(const void* ei, int e, int& src, int& dst) {
    if (g_flags[0]) {
        const long long* p = (const long long*)ei;
        src = (int)p[e]; dst = (int)p[N_EDGES + e];
    } else {
        const int* p = (const int*)ei;
        src = p[e]; dst = p[N_EDGES + e];
    }
}

// ------------- per-layer edge attention projection: ae[l][f][h] ----------
__global__ void attproj_kernel(const float* __restrict__ we0, const float* __restrict__ at0,
                               const float* __restrict__ we1, const float* __restrict__ at1,
                               const float* __restrict__ we2, const float* __restrict__ at2) {
    int t = threadIdx.x;
    if (t >= 36) return;
    int l = t / 12, r = t % 12, f = r / 2, h = r % 2;
    const float* we = (l == 0) ? we0 : (l == 1) ? we1 : we2;
    const float* at = (l == 0) ? at0 : (l == 1) ? at1 : at2;
    float s = 0.f;
    #pragma unroll
    for (int c = 0; c < 64; c++)
        s += we[f * 128 + h * 64 + c] * at[h * 192 + 128 + c];
    g_ae[t] = s;
}

// ------------- per-edge edge-att scores for ALL 3 layers (coalesced) -----
__global__ void se_kernel(const float* __restrict__ ea) {
    int e = blockIdx.x * blockDim.x + threadIdx.x;
    if (e >= N_EDGES) return;
    float f[6];
    #pragma unroll
    for (int k = 0; k < 6; k++) f[k] = ea[e * 6 + k];
    #pragma unroll
    for (int l = 0; l < 3; l++) {
        const float* ap = g_ae + l * 12;
        float s0 = 0.f, s1 = 0.f;
        #pragma unroll
        for (int k = 0; k < 6; k++) { s0 += f[k] * ap[k * 2]; s1 += f[k] * ap[k * 2 + 1]; }
        g_se[e * 6 + l * 2]     = s0;
        g_se[e * 6 + l * 2 + 1] = s1;
    }
}

// ---------------------------- CSR build ----------------------------------
__global__ void deg_kernel(const void* __restrict__ ei) {
    int e = blockIdx.x * blockDim.x + threadIdx.x;
    if (e >= N_EDGES) return;
    int src, dst; load_edge(ei, e, src, dst);
    atomicAdd(&g_deg[dst], 1);
}

__global__ void scan_kernel() {
    __shared__ int sums[1024];
    const int C = 49;                       // 1024*49 >= 50000
    int t = threadIdx.x, base = t * C;
    int s = 0;
    for (int k = 0; k < C; k++) { int i = base + k; if (i < N_NODES) s += g_deg[i]; }
    sums[t] = s; __syncthreads();
    for (int off = 1; off < 1024; off <<= 1) {
        int v = (t >= off) ? sums[t - off] : 0;
        __syncthreads();
        sums[t] += v;
        __syncthreads();
    }
    int run = (t == 0) ? 0 : sums[t - 1];
    for (int k = 0; k < C; k++) {
        int i = base + k;
        if (i < N_NODES) { g_off[i] = run; g_cur[i] = run; run += g_deg[i]; }
    }
    if (t == 1023) g_off[N_NODES] = sums[1023];
}

__global__ void scatter_kernel(const void* __restrict__ ei) {
    int e = blockIdx.x * blockDim.x + threadIdx.x;
    if (e >= N_EDGES) return;
    int src, dst; load_edge(ei, e, src, dst);
    int pos = atomicAdd(&g_cur[dst], 1);
    g_srcs[pos] = src;
    g_perm[e] = pos;
}

// ---------------- layer-0 lin: x(N,7) @ w(7,128) -> g_xp -----------------
__global__ void lin0_kernel(const float* __restrict__ x, const float* __restrict__ w) {
    int idx = blockIdx.x * blockDim.x + threadIdx.x;
    if (idx >= N_NODES * D) return;
    int n = idx >> 7, c = idx & 127;
    const float* xr = x + n * 7;
    float s = 0.f;
    #pragma unroll
    for (int f = 0; f < 7; f++) s += xr[f] * w[f * 128 + c];
    g_xp[idx] = s;
}

// ------------- per-node attention dots (layer 0 only; fused elsewhere) ---
__global__ void s_kernel(const float* __restrict__ att) {
    int gw   = (blockIdx.x * blockDim.x + threadIdx.x) >> 5;
    int lane = threadIdx.x & 31;
    if (gw >= N_NODES) return;
    const float* xr = g_xp + gw * 128;
    float v0 = xr[lane], v1 = xr[lane + 32], v2 = xr[lane + 64], v3 = xr[lane + 96];
    float si0 = v0 * att[lane]            + v1 * att[lane + 32];
    float sj0 = v0 * att[64 + lane]       + v1 * att[96 + lane];
    float si1 = v2 * att[192 + lane]      + v3 * att[192 + lane + 32];
    float sj1 = v2 * att[192 + 64 + lane] + v3 * att[192 + 96 + lane];
    #pragma unroll
    for (int o = 16; o; o >>= 1) {
        si0 += __shfl_down_sync(0xffffffffu, si0, o);
        sj0 += __shfl_down_sync(0xffffffffu, sj0, o);
        si1 += __shfl_down_sync(0xffffffffu, si1, o);
        sj1 += __shfl_down_sync(0xffffffffu, sj1, o);
    }
    if (lane == 0) {
        g_si[gw] = make_float2(si0, si1);
        g_sj[gw] = make_float2(sj0, sj1);
    }
}

// ------------- lin: h(N,128) @ w(128,128) -> g_xp, + fused s-dots --------
__global__ void lin128_kernel(const float* __restrict__ hin, const float* __restrict__ w,
                              const float* __restrict__ att) {
    __shared__ float Xs[64][33];
    __shared__ float Ws[32][128];
    int t = threadIdx.x;
    int tcol = t & 15, trow = t >> 4;
    int row0 = blockIdx.x * 64;
    float acc[4][8];
    #pragma unroll
    for (int i = 0; i < 4; i++)
        #pragma unroll
        for (int j = 0; j < 8; j++) acc[i][j] = 0.f;

    for (int kc = 0; kc < 4; kc++) {
        int k0 = kc * 32;
        for (int i = t; i < 64 * 32; i += 256) {
            int r = i >> 5, k = i & 31, row = row0 + r;
            Xs[r][k] = (row < N_NODES) ? hin[row * 128 + k0 + k] : 0.f;
        }
        for (int i = t; i < 32 * 128; i += 256) {
            int kk = i >> 7, c = i & 127;
            Ws[kk][c] = w[(k0 + kk) * 128 + c];
        }
        __syncthreads();
        #pragma unroll
        for (int kk = 0; kk < 32; kk++) {
            float xv[4];
            #pragma unroll
            for (int i = 0; i < 4; i++) xv[i] = Xs[trow * 4 + i][kk];
            #pragma unroll
            for (int j = 0; j < 8; j++) {
                float wv = Ws[kk][tcol + 16 * j];
                #pragma unroll
                for (int i = 0; i < 4; i++) acc[i][j] += xv[i] * wv;
            }
        }
        __syncthreads();
    }
    // store xp
    #pragma unroll
    for (int i = 0; i < 4; i++) {
        int row = row0 + trow * 4 + i;
        if (row < N_NODES) {
            #pragma unroll
            for (int j = 0; j < 8; j++)
                g_xp[row * 128 + tcol + 16 * j] = acc[i][j];
        }
    }
    // fused s-dots: partial per thread over its 8 cols, reduce across 16 lanes
    float psi0[4] = {0,0,0,0}, psi1[4] = {0,0,0,0};
    float psj0[4] = {0,0,0,0}, psj1[4] = {0,0,0,0};
    #pragma unroll
    for (int j = 0; j < 8; j++) {
        int c = tcol + 16 * j;
        int h = c >> 6, cc = c & 63;
        float ai = att[h * 192 + cc];
        float aj = att[h * 192 + 64 + cc];
        #pragma unroll
        for (int i = 0; i < 4; i++) {
            float v = acc[i][j];
            if (h == 0) { psi0[i] += v * ai; psj0[i] += v * aj; }
            else        { psi1[i] += v * ai; psj1[i] += v * aj; }
        }
    }
    #pragma unroll
    for (int i = 0; i < 4; i++) {
        #pragma unroll
        for (int o = 8; o; o >>= 1) {
            psi0[i] += __shfl_down_sync(0xffffffffu, psi0[i], o, 16);
            psi1[i] += __shfl_down_sync(0xffffffffu, psi1[i], o, 16);
            psj0[i] += __shfl_down_sync(0xffffffffu, psj0[i], o, 16);
            psj1[i] += __shfl_down_sync(0xffffffffu, psj1[i], o, 16);
        }
    }
    if (tcol == 0) {
        #pragma unroll
        for (int i = 0; i < 4; i++) {
            int row = row0 + trow * 4 + i;
            if (row < N_NODES) {
                g_si[row] = make_float2(psi0[i], psi1[i]);
                g_sj[row] = make_float2(psj0[i], psj1[i]);
            }
        }
    }
}

// ------------- alpha: 1 thread/edge, write weights in dst-sorted order ---
__global__ void alpha_kernel(const void* __restrict__ ei, int layer) {
    int e = blockIdx.x * blockDim.x + threadIdx.x;
    if (e >= N_EDGES) return;
    int src, dst; load_edge(ei, e, src, dst);
    float2 se = *(const float2*)(g_se + e * 6 + layer * 2);
    float2 si = g_si[dst];
    float2 sj = g_sj[src];
    float a0 = si.x + sj.x + se.x;
    float a1 = si.y + sj.y + se.y;
    a0 = a0 > 0.f ? a0 : 0.2f * a0;
    a1 = a1 > 0.f ? a1 : 0.2f * a1;
    float m  = fmaxf(a0, a1);
    float e0 = __expf(a0 - m), e1 = __expf(a1 - m);
    float inv = 1.f / (e0 + e1);
    g_ws[g_perm[e]] = make_float2(e0 * inv, e1 * inv);
}

// ------------- aggregate: warp per dst node, no atomics, fused bias+relu -
__global__ void agg_kernel(const float* __restrict__ b) {
    int node = (blockIdx.x * blockDim.x + threadIdx.x) >> 5;
    int lane = threadIdx.x & 31;
    if (node >= N_NODES) return;
    int beg = g_off[node], end = g_off[node + 1];
    float4 acc = make_float4(0.f, 0.f, 0.f, 0.f);
    for (int i = beg; i < end; i++) {
        int src   = g_srcs[i];
        float2 wv = g_ws[i];
        float a   = (lane < 16) ? wv.x : wv.y;
        float4 v  = ((const float4*)(g_xp + (size_t)src * 128))[lane];
        acc.x += a * v.x; acc.y += a * v.y; acc.z += a * v.z; acc.w += a * v.w;
    }
    float4 bv = ((const float4*)b)[lane];
    acc.x = fmaxf(acc.x + bv.x, 0.f);
    acc.y = fmaxf(acc.y + bv.y, 0.f);
    acc.z = fmaxf(acc.z + bv.z, 0.f);
    acc.w = fmaxf(acc.w + bv.w, 0.f);
    ((float4*)(g_h + (size_t)node * 128))[lane] = acc;
}

// ------------- mean pool: batch is sorted, run-length local accum --------
__global__ void pool_kernel(const void* __restrict__ batch) {
    const int NPB = 128;
    int t  = threadIdx.x;
    int n0 = blockIdx.x * NPB;
    int is64 = g_flags[1];
    float acc = 0.f; int cur = -1; int run = 0;
    for (int k = 0; k < NPB; k++) {
        int n = n0 + k;
        if (n >= N_NODES) break;
        int g = is64 ? (int)((const long long*)batch)[n] : ((const int*)batch)[n];
        if (g != cur) {
            if (cur >= 0) {
                atomicAdd(&g_pool[cur * D + t], acc);
                if (t == 0) atomicAdd(&g_cnt[cur], (float)run);
            }
            acc = 0.f; run = 0; cur = g;
        }
        acc += g_h[n * D + t]; run++;
    }
    if (cur >= 0) {
        atomicAdd(&g_pool[cur * D + t], acc);
        if (t == 0) atomicAdd(&g_cnt[cur], (float)run);
    }
}

// ------------- final: mean, linear(128->2), log_softmax ------------------
__global__ void final_kernel(const float* __restrict__ wout,
                             const float* __restrict__ bout,
                             float* __restrict__ out) {
    int g = threadIdx.x;
    if (g >= N_GRAPHS) return;
    float inv = 1.f / fmaxf(g_cnt[g], 1.f);
    float z0 = bout[0], z1 = bout[1];
    for (int c = 0; c < D; c++) {
        float p = g_pool[g * D + c] * inv;
        z0 += p * wout[c * 2];
        z1 += p * wout[c * 2 + 1];
    }
    float m = fmaxf(z0, z1);
    float l = m + logf(expf(z0 - m) + expf(z1 - m));
    out[g * 2]     = z0 - l;
    out[g * 2 + 1] = z1 - l;
}

// ------------------------------ launch -----------------------------------
extern "C" void kernel_launch(void* const* d_in, const int* in_sizes, int n_in,
                              void* d_out, int out_size) {
    const float* x     = (const float*)d_in[0];
    const void*  ei    = d_in[1];
    const float* ea    = (const float*)d_in[2];
    const void*  batch = d_in[3];
    const float* wl[3]  = { (const float*)d_in[4],  (const float*)d_in[8],  (const float*)d_in[12] };
    const float* we[3]  = { (const float*)d_in[5],  (const float*)d_in[9],  (const float*)d_in[13] };
    const float* att[3] = { (const float*)d_in[6],  (const float*)d_in[10], (const float*)d_in[14] };
    const float* bb[3]  = { (const float*)d_in[7],  (const float*)d_in[11], (const float*)d_in[15] };
    const float* wout = (const float*)d_in[16];
    const float* bout = (const float*)d_in[17];

    void *p_h = nullptr, *p_pool = nullptr, *p_cnt = nullptr, *p_deg = nullptr;
    cudaGetSymbolAddress(&p_h,    g_h);
    cudaGetSymbolAddress(&p_pool, g_pool);
    cudaGetSymbolAddress(&p_cnt,  g_cnt);
    cudaGetSymbolAddress(&p_deg,  g_deg);

    const int EB = (N_EDGES + 255) / 256;

    detect_kernel<<<1, 64>>>((const int*)ei, (const int*)batch);
    attproj_kernel<<<1, 64>>>(we[0], att[0], we[1], att[1], we[2], att[2]);
    se_kernel<<<EB, 256>>>(ea);

    // CSR build (once per call)
    cudaMemsetAsync(p_deg, 0, (size_t)N_NODES * sizeof(int));
    deg_kernel<<<EB, 256>>>(ei);
    scan_kernel<<<1, 1024>>>();
    scatter_kernel<<<EB, 256>>>(ei);

    const int ND = N_NODES * D;
    for (int l = 0; l < 3; l++) {
        if (l == 0) {
            lin0_kernel<<<(ND + 255) / 256, 256>>>(x, wl[0]);
            s_kernel<<<(N_NODES * 32 + 255) / 256, 256>>>(att[0]);
        } else {
            lin128_kernel<<<(N_NODES + 63) / 64, 256>>>((const float*)p_h, wl[l], att[l]);
        }
        alpha_kernel<<<EB, 256>>>(ei, l);
        agg_kernel<<<(N_NODES * 32 + 255) / 256, 256>>>(bb[l]);
    }

    cudaMemsetAsync(p_pool, 0, (size_t)N_GRAPHS * D * sizeof(float));
    cudaMemsetAsync(p_cnt,  0, (size_t)N_GRAPHS * sizeof(float));
    pool_kernel<<<(N_NODES + 127) / 128, 128>>>(batch);
    final_kernel<<<1, 64>>>(wout, bout, (float*)d_out);
}